// round 4
// baseline (speedup 1.0000x reference)
#include <cuda_runtime.h>
#include <math.h>

#define NB   32      // batch
#define NT   4096    // sequence
#define NCAT 128
#define NNE  512
#define NHS  64

#define WARPS 8
#define CHUNK 32             // rows per block in fused kernel
#define NCH  (NT / CHUNK)    // 128 chunks per batch
#define ROWS_PER_WARP (CHUNK / WARPS)  // 4

// ---- scratch (device globals; no allocations allowed) ----
__device__ float g_qk[NB * NNE];             // folded scale * Wk @ (cat_emb @ Wq)
__device__ float g_pm[NB * NCH];             // per-chunk local max
__device__ float g_ps[NB * NCH];             // per-chunk exp-sum (w.r.t. local max)
__device__ float g_pacc[(size_t)NB * NCH * NNE];  // per-chunk weighted sums
__device__ float g_y[NB * NNE];              // final per-batch row

// ============================================================
// Kernel A: q[b] = cat_emb[b] @ Wq ; qk[b,n] = scale * sum_h Wk[n,h] q[h]
// ============================================================
__global__ void kA(const float* __restrict__ cat_emb,
                   const float* __restrict__ Wq,
                   const float* __restrict__ Wk) {
    const int b = blockIdx.x;
    const int tid = threadIdx.x;
    __shared__ float qs[NHS];

    if (tid < NHS) {
        float acc = 0.f;
        const float* ce = cat_emb + b * NCAT;
        #pragma unroll 8
        for (int c = 0; c < NCAT; ++c)
            acc += ce[c] * Wq[c * NHS + tid];
        qs[tid] = acc;
    }
    __syncthreads();

    float acc = 0.f;
    const float* wkr = Wk + tid * NHS;
    #pragma unroll
    for (int h = 0; h < NHS; ++h)
        acc += wkr[h] * qs[h];
    g_qk[b * NNE + tid] = acc * 0.125f;  // 1/sqrt(64)
}

// ============================================================
// Fused kernel v2: one DRAM pass, smem-staged.
//  Phase 1 (kB pattern): warp-per-row dot -> scores; rows -> smem.
//  Local softmax over 32 rows (warp 0).
//  Phase 2 (kD pattern): thread-per-column weighted sum from smem.
// grid: (NCH, NB), 256 threads, 64 KB dynamic smem.
// ============================================================
extern __shared__ float sx[];  // CHUNK * NNE floats = 64 KB

__global__ void kFuse2(const float* __restrict__ x) {
    const int b = blockIdx.y;
    const int ch = blockIdx.x;
    const int tid = threadIdx.x;
    const int warp = tid >> 5, lane = tid & 31;

    __shared__ float sqk[NNE];
    __shared__ float sscore[CHUNK];
    __shared__ float sw[CHUNK];

    sqk[tid]       = g_qk[b * NNE + tid];
    sqk[tid + 256] = g_qk[b * NNE + tid + 256];
    __syncthreads();

    // qk registers in row lane-layout
    float4 qv[4];
    const float4* sqk4 = reinterpret_cast<const float4*>(sqk);
    #pragma unroll
    for (int i = 0; i < 4; ++i) qv[i] = sqk4[lane + 32 * i];

    const float4* xbase = reinterpret_cast<const float4*>(
        x + ((size_t)b * NT + (size_t)ch * CHUNK) * NNE);
    float4* sx4 = reinterpret_cast<float4*>(sx);

    // ---- phase 1: load rows, stage to smem, compute scores ----
    #pragma unroll
    for (int j = 0; j < ROWS_PER_WARP; ++j) {
        const int t = warp + WARPS * j;
        const float4* xr = xbase + (size_t)t * (NNE / 4);
        float4 xv[4];
        #pragma unroll
        for (int i = 0; i < 4; ++i) xv[i] = xr[lane + 32 * i];

        float d = 0.f;
        #pragma unroll
        for (int i = 0; i < 4; ++i)
            d += xv[i].x * qv[i].x + xv[i].y * qv[i].y +
                 xv[i].z * qv[i].z + xv[i].w * qv[i].w;

        #pragma unroll
        for (int i = 0; i < 4; ++i)
            sx4[(size_t)t * (NNE / 4) + lane + 32 * i] = xv[i];

        #pragma unroll
        for (int o = 16; o > 0; o >>= 1)
            d += __shfl_xor_sync(0xffffffffu, d, o);
        if (lane == 0) sscore[t] = d;
    }
    __syncthreads();

    // ---- local softmax over CHUNK=32 scores (warp 0, lane t) ----
    if (tid < 32) {
        const float s = sscore[tid];
        float m = s;
        #pragma unroll
        for (int o = 16; o > 0; o >>= 1)
            m = fmaxf(m, __shfl_xor_sync(0xffffffffu, m, o));
        const float e = __expf(s - m);
        float S = e;
        #pragma unroll
        for (int o = 16; o > 0; o >>= 1)
            S += __shfl_xor_sync(0xffffffffu, S, o);
        sw[tid] = e;
        if (tid == 0) {
            g_pm[b * NCH + ch] = m;
            g_ps[b * NCH + ch] = S;
        }
    }
    __syncthreads();

    // ---- phase 2: thread-per-column weighted sum from smem ----
    float a0 = 0.f, a1 = 0.f;
    #pragma unroll
    for (int t = 0; t < CHUNK; ++t) {
        const float wt = sw[t];
        a0 = fmaf(wt, sx[(size_t)t * NNE + tid],       a0);
        a1 = fmaf(wt, sx[(size_t)t * NNE + tid + 256], a1);
    }
    float* p = g_pacc + (size_t)(b * NCH + ch) * NNE;
    p[tid]       = a0;
    p[tid + 256] = a1;
}

// ============================================================
// Kernel E: combine 128 partials -> xa; xa@Wv -> out; out@Wp -> y; LayerNorm
// grid: NB blocks, 512 threads
// ============================================================
__global__ void kE(const float* __restrict__ Wv,
                   const float* __restrict__ Wp,
                   const float* __restrict__ gamma,
                   const float* __restrict__ beta) {
    const int b = blockIdx.x;
    const int tid = threadIdx.x;
    const int warp = tid >> 5, lane = tid & 31;

    __shared__ float spm[NCH], sps[NCH], sf[NCH];
    __shared__ float xa[NNE];
    __shared__ float outh[NHS];
    __shared__ float red[16];
    __shared__ float bcast;

    if (tid < NCH) {
        spm[tid] = g_pm[b * NCH + tid];
        sps[tid] = g_ps[b * NCH + tid];
    }
    __syncthreads();

    float mb = -INFINITY;
    #pragma unroll 8
    for (int c = 0; c < NCH; ++c) mb = fmaxf(mb, spm[c]);

    if (tid < NCH) sf[tid] = __expf(spm[tid] - mb);
    __syncthreads();

    float Sb = 0.f;
    #pragma unroll 8
    for (int c = 0; c < NCH; ++c) Sb += sps[c] * sf[c];

    float acc = 0.f;
    #pragma unroll 8
    for (int c = 0; c < NCH; ++c)
        acc += g_pacc[(size_t)(b * NCH + c) * NNE + tid] * sf[c];
    xa[tid] = acc / Sb;
    __syncthreads();

    if (tid < NHS) {
        float o = 0.f;
        #pragma unroll 8
        for (int n = 0; n < NNE; ++n)
            o += xa[n] * Wv[n * NHS + tid];
        outh[tid] = o;
    }
    __syncthreads();

    float y = 0.f;
    #pragma unroll
    for (int h = 0; h < NHS; ++h)
        y += outh[h] * Wp[h * NNE + tid];

    // mean
    float s = y;
    #pragma unroll
    for (int o = 16; o > 0; o >>= 1)
        s += __shfl_xor_sync(0xffffffffu, s, o);
    if (lane == 0) red[warp] = s;
    __syncthreads();
    if (tid < 32) {
        float ss2 = (tid < 16) ? red[tid] : 0.f;
        #pragma unroll
        for (int o = 16; o > 0; o >>= 1)
            ss2 += __shfl_xor_sync(0xffffffffu, ss2, o);
        if (tid == 0) bcast = ss2;
    }
    __syncthreads();
    const float mu = bcast * (1.f / NNE);
    __syncthreads();

    // variance
    const float d = y - mu;
    float vs = d * d;
    #pragma unroll
    for (int o = 16; o > 0; o >>= 1)
        vs += __shfl_xor_sync(0xffffffffu, vs, o);
    if (lane == 0) red[warp] = vs;
    __syncthreads();
    if (tid < 32) {
        float ss2 = (tid < 16) ? red[tid] : 0.f;
        #pragma unroll
        for (int o = 16; o > 0; o >>= 1)
            ss2 += __shfl_xor_sync(0xffffffffu, ss2, o);
        if (tid == 0) bcast = ss2;
    }
    __syncthreads();
    const float var = bcast * (1.f / NNE);
    const float rstd = rsqrtf(var + 1e-5f);

    g_y[b * NNE + tid] = d * rstd * gamma[tid] + beta[tid];
}

// ============================================================
// Kernel F: broadcast g_y[b,:] to out[b, t, :]; streaming float4 stores
// ============================================================
#define ROWS_F 64
__global__ void kF(float* __restrict__ out) {
    const int b = blockIdx.y;
    const int tid = threadIdx.x;          // 256
    const int col = tid & 127;
    const int half = tid >> 7;

    const float4 val = reinterpret_cast<const float4*>(g_y + b * NNE)[col];

    const int t0 = blockIdx.x * ROWS_F;
    float4* o = reinterpret_cast<float4*>(out + ((size_t)b * NT + t0) * NNE);
    #pragma unroll 8
    for (int r = 0; r < ROWS_F / 2; ++r)
        __stcs(&o[(size_t)(r * 2 + half) * (NNE / 4) + col], val);
}

// ============================================================
extern "C" void kernel_launch(void* const* d_in, const int* in_sizes, int n_in,
                              void* d_out, int out_size) {
    const float* x       = (const float*)d_in[0];
    const float* cat_emb = (const float*)d_in[1];
    const float* Wq      = (const float*)d_in[2];
    const float* Wk      = (const float*)d_in[3];
    const float* Wv      = (const float*)d_in[4];
    const float* Wp      = (const float*)d_in[5];
    const float* gamma   = (const float*)d_in[6];
    const float* beta    = (const float*)d_in[7];
    float* out = (float*)d_out;

    const int dyn_smem = CHUNK * NNE * (int)sizeof(float);  // 64 KB
    cudaFuncSetAttribute(kFuse2, cudaFuncAttributeMaxDynamicSharedMemorySize,
                         dyn_smem);

    kA<<<NB, NNE>>>(cat_emb, Wq, Wk);
    kFuse2<<<dim3(NCH, NB), 256, dyn_smem>>>(x);
    kE<<<NB, NNE>>>(Wv, Wp, gamma, beta);
    kF<<<dim3(NT / ROWS_F, NB), 256>>>(out);
}

// round 5
// speedup vs baseline: 1.3799x; 1.3799x over previous
#include <cuda_runtime.h>
#include <math.h>

#define NB   32      // batch
#define NT   4096    // sequence
#define NCAT 128
#define NNE  512
#define NHS  64

#define CHR  16              // rows per block in fused kernel
#define NCHF (NT / CHR)      // 256 chunks per batch

// ---- scratch (device globals; no allocations allowed) ----
__device__ float g_qk[NB * NNE];                   // scale * Wk @ (cat_emb @ Wq)
__device__ float g_pm[NB * NCHF];                  // per-chunk local max
__device__ float g_ps[NB * NCHF];                  // per-chunk exp-sum
__device__ float g_pacc[(size_t)NB * NCHF * NNE];  // per-chunk weighted sums (16.8 MB)
__device__ float g_y[NB * NNE];                    // final per-batch row

// ============================================================
// Kernel A (parallelized): q = cat_emb@Wq ; qk[n] = 0.125 * Wk[n,:]·q
// grid: NB, 512 threads
// ============================================================
__global__ void kA(const float* __restrict__ cat_emb,
                   const float* __restrict__ Wq,
                   const float* __restrict__ Wk) {
    const int b = blockIdx.x;
    const int tid = threadIdx.x;
    const int h = tid & 63;
    const int part = tid >> 6;  // 8 parts x 16 c each

    __shared__ float qpart[8][NHS];
    __shared__ float qs[NHS];

    float a = 0.f;
    const float* ce = cat_emb + b * NCAT;
    #pragma unroll
    for (int c = part * 16; c < part * 16 + 16; ++c)
        a += ce[c] * Wq[c * NHS + h];
    qpart[part][h] = a;
    __syncthreads();

    if (tid < NHS) {
        float q = 0.f;
        #pragma unroll
        for (int p = 0; p < 8; ++p) q += qpart[p][tid];
        qs[tid] = q * 0.125f;  // fold 1/sqrt(64)
    }
    __syncthreads();

    // qk[n], n = tid: float4 dot of Wk row with qs
    const float4* wk4 = reinterpret_cast<const float4*>(Wk + tid * NHS);
    const float4* q4  = reinterpret_cast<const float4*>(qs);
    float acc = 0.f;
    #pragma unroll
    for (int i = 0; i < 16; ++i) {
        const float4 w = wk4[i];
        const float4 qq = q4[i];
        acc += w.x * qq.x + w.y * qq.y + w.z * qq.z + w.w * qq.w;
    }
    g_qk[b * NNE + tid] = acc;
}

// ============================================================
// Fused kernel v3: 16-row chunks, smem-staged, one DRAM pass.
// grid: (NCHF, NB), 256 threads (8 warps), 32 KB static smem.
// Phase 1: warp-per-row loads -> smem + scores. Local softmax.
// Phase 2: thread-per-column weighted sum from smem.
// ============================================================
__global__ void kFuse3(const float* __restrict__ x) {
    const int b = blockIdx.y;
    const int ch = blockIdx.x;
    const int tid = threadIdx.x;
    const int warp = tid >> 5, lane = tid & 31;

    __shared__ float sx[CHR * NNE];   // 32 KB
    __shared__ float sscore[32];      // first 16 real, rest -inf pad
    __shared__ float sw[CHR];

    if (tid >= 16 && tid < 32) sscore[tid] = -INFINITY;

    const float4* qkp = reinterpret_cast<const float4*>(g_qk + b * NNE);
    float4 qv[4];
    #pragma unroll
    for (int i = 0; i < 4; ++i) qv[i] = qkp[lane + 32 * i];

    const float4* xbase = reinterpret_cast<const float4*>(
        x + ((size_t)b * NT + (size_t)ch * CHR) * NNE);
    float4* sx4 = reinterpret_cast<float4*>(sx);

    // ---- phase 1: 2 rows per warp ----
    #pragma unroll
    for (int j = 0; j < 2; ++j) {
        const int t = warp + 8 * j;
        const float4* xr = xbase + (size_t)t * (NNE / 4);
        float4 xv[4];
        #pragma unroll
        for (int i = 0; i < 4; ++i) xv[i] = xr[lane + 32 * i];

        float d = 0.f;
        #pragma unroll
        for (int i = 0; i < 4; ++i)
            d += xv[i].x * qv[i].x + xv[i].y * qv[i].y +
                 xv[i].z * qv[i].z + xv[i].w * qv[i].w;

        #pragma unroll
        for (int i = 0; i < 4; ++i)
            sx4[t * (NNE / 4) + lane + 32 * i] = xv[i];

        #pragma unroll
        for (int o = 16; o > 0; o >>= 1)
            d += __shfl_xor_sync(0xffffffffu, d, o);
        if (lane == 0) sscore[t] = d;
    }
    __syncthreads();

    // ---- local softmax over 16 scores (warp 0) ----
    if (tid < 32) {
        const float s = sscore[tid];
        float m = s;
        #pragma unroll
        for (int o = 16; o > 0; o >>= 1)
            m = fmaxf(m, __shfl_xor_sync(0xffffffffu, m, o));
        const float e = (tid < CHR) ? __expf(s - m) : 0.f;
        float S = e;
        #pragma unroll
        for (int o = 16; o > 0; o >>= 1)
            S += __shfl_xor_sync(0xffffffffu, S, o);
        if (tid < CHR) sw[tid] = e;
        if (tid == 0) {
            g_pm[b * NCHF + ch] = m;
            g_ps[b * NCHF + ch] = S;
        }
    }
    __syncthreads();

    // ---- phase 2: thread-per-column weighted sum from smem ----
    float a0 = 0.f, a1 = 0.f;
    #pragma unroll
    for (int t = 0; t < CHR; ++t) {
        const float wt = sw[t];
        a0 = fmaf(wt, sx[t * NNE + tid],       a0);
        a1 = fmaf(wt, sx[t * NNE + tid + 256], a1);
    }
    float* p = g_pacc + (size_t)(b * NCHF + ch) * NNE;
    p[tid]       = a0;
    p[tid + 256] = a1;
}

// ============================================================
// Kernel E (parallelized): combine 256 partials -> xa; xa@Wv; @Wp; LayerNorm
// grid: NB, 1024 threads
// ============================================================
__global__ void kE(const float* __restrict__ Wv,
                   const float* __restrict__ Wp,
                   const float* __restrict__ gamma,
                   const float* __restrict__ beta) {
    const int b = blockIdx.x;
    const int tid = threadIdx.x;
    const int warp = tid >> 5, lane = tid & 31;

    __shared__ float spm[NCHF], sps[NCHF], sf[NCHF];
    __shared__ float xph[NNE];     // half-1 partial
    __shared__ float xa[NNE];
    __shared__ float wpart[16][NHS];
    __shared__ float outh[NHS];
    __shared__ float red[32];
    __shared__ float bcast;

    if (tid < NCHF) {
        spm[tid] = g_pm[b * NCHF + tid];
        sps[tid] = g_ps[b * NCHF + tid];
    }
    __syncthreads();

    float mb = -INFINITY;
    #pragma unroll 8
    for (int c = 0; c < NCHF; ++c) mb = fmaxf(mb, spm[c]);

    if (tid < NCHF) sf[tid] = __expf(spm[tid] - mb);
    __syncthreads();

    float Sb = 0.f;
    #pragma unroll 8
    for (int c = 0; c < NCHF; ++c) Sb += sps[c] * sf[c];

    // 2-way split of the 256-chunk reduction per column
    const int col = tid & 511;
    const int half = tid >> 9;
    float acc = 0.f;
    {
        const float* pp = g_pacc + (size_t)(b * NCHF + half * 128) * NNE + col;
        const float* f  = sf + half * 128;
        #pragma unroll 8
        for (int c = 0; c < 128; ++c)
            acc = fmaf(pp[(size_t)c * NNE], f[c], acc);
    }
    if (half) xph[col] = acc;
    __syncthreads();
    if (tid < NNE) xa[tid] = (acc + xph[tid]) / Sb;
    __syncthreads();

    // Wv GEMM: out[h] = sum_n xa[n]*Wv[n,h]; 16-way n-split
    {
        const int h = tid & 63;
        const int part = tid >> 6;  // 16 parts x 32 n
        float po = 0.f;
        #pragma unroll
        for (int n = part * 32; n < part * 32 + 32; ++n)
            po = fmaf(xa[n], Wv[n * NHS + h], po);
        wpart[part][h] = po;
    }
    __syncthreads();
    if (tid < NHS) {
        float o = 0.f;
        #pragma unroll
        for (int p = 0; p < 16; ++p) o += wpart[p][tid];
        outh[tid] = o;
    }
    __syncthreads();

    float y = 0.f;
    if (tid < NNE) {
        #pragma unroll
        for (int h2 = 0; h2 < NHS; ++h2)
            y = fmaf(outh[h2], Wp[h2 * NNE + tid], y);
    }

    // LayerNorm over the 512 y-values (threads >= 512 contribute 0)
    float s = (tid < NNE) ? y : 0.f;
    #pragma unroll
    for (int o = 16; o > 0; o >>= 1)
        s += __shfl_xor_sync(0xffffffffu, s, o);
    if (lane == 0) red[warp] = s;
    __syncthreads();
    if (tid < 32) {
        float ss2 = red[tid];
        #pragma unroll
        for (int o = 16; o > 0; o >>= 1)
            ss2 += __shfl_xor_sync(0xffffffffu, ss2, o);
        if (tid == 0) bcast = ss2;
    }
    __syncthreads();
    const float mu = bcast * (1.f / NNE);
    __syncthreads();

    const float d = (tid < NNE) ? (y - mu) : 0.f;
    float vs = d * d;
    #pragma unroll
    for (int o = 16; o > 0; o >>= 1)
        vs += __shfl_xor_sync(0xffffffffu, vs, o);
    if (lane == 0) red[warp] = vs;
    __syncthreads();
    if (tid < 32) {
        float ss2 = red[tid];
        #pragma unroll
        for (int o = 16; o > 0; o >>= 1)
            ss2 += __shfl_xor_sync(0xffffffffu, ss2, o);
        if (tid == 0) bcast = ss2;
    }
    __syncthreads();
    const float var = bcast * (1.f / NNE);
    const float rstd = rsqrtf(var + 1e-5f);

    if (tid < NNE)
        g_y[b * NNE + tid] = d * rstd * gamma[tid] + beta[tid];
}

// ============================================================
// Kernel F: broadcast g_y[b,:] to out[b, t, :]; streaming float4 stores
// ============================================================
#define ROWS_F 64
__global__ void kF(float* __restrict__ out) {
    const int b = blockIdx.y;
    const int tid = threadIdx.x;          // 256
    const int col = tid & 127;
    const int half = tid >> 7;

    const float4 val = reinterpret_cast<const float4*>(g_y + b * NNE)[col];

    const int t0 = blockIdx.x * ROWS_F;
    float4* o = reinterpret_cast<float4*>(out + ((size_t)b * NT + t0) * NNE);
    #pragma unroll 8
    for (int r = 0; r < ROWS_F / 2; ++r)
        __stcs(&o[(size_t)(r * 2 + half) * (NNE / 4) + col], val);
}

// ============================================================
extern "C" void kernel_launch(void* const* d_in, const int* in_sizes, int n_in,
                              void* d_out, int out_size) {
    const float* x       = (const float*)d_in[0];
    const float* cat_emb = (const float*)d_in[1];
    const float* Wq      = (const float*)d_in[2];
    const float* Wk      = (const float*)d_in[3];
    const float* Wv      = (const float*)d_in[4];
    const float* Wp      = (const float*)d_in[5];
    const float* gamma   = (const float*)d_in[6];
    const float* beta    = (const float*)d_in[7];
    float* out = (float*)d_out;

    kA<<<NB, 512>>>(cat_emb, Wq, Wk);
    kFuse3<<<dim3(NCHF, NB), 256>>>(x);
    kE<<<NB, 1024>>>(Wv, Wp, gamma, beta);
    kF<<<dim3(NT / ROWS_F, NB), 256>>>(out);
}

// round 6
// speedup vs baseline: 1.4180x; 1.0276x over previous
#include <cuda_runtime.h>
#include <math.h>

#define NB   32      // batch
#define NT   4096    // sequence
#define NCAT 128
#define NNE  512
#define NHS  64

#define CHR  16              // rows per block in fused kernel
#define NCHF (NT / CHR)      // 256 chunks per batch

// ---- scratch (device globals; no allocations allowed) ----
__device__ float g_qk[NB * NNE];                   // scale * Wk @ (cat_emb @ Wq)
__device__ float g_pm[NB * NCHF];                  // per-chunk local max
__device__ float g_ps[NB * NCHF];                  // per-chunk exp-sum
__device__ float g_pacc[(size_t)NB * NCHF * NNE];  // per-chunk weighted sums
__device__ float g_y[NB * NNE];                    // final per-batch row

// ============================================================
// Kernel A: q = cat_emb@Wq ; qk[n] = 0.125 * Wk[n,:]·q
// grid: NB, 512 threads
// ============================================================
__global__ void kA(const float* __restrict__ cat_emb,
                   const float* __restrict__ Wq,
                   const float* __restrict__ Wk) {
    const int b = blockIdx.x;
    const int tid = threadIdx.x;
    const int h = tid & 63;
    const int part = tid >> 6;  // 8 parts x 16 c each

    __shared__ float qpart[8][NHS];
    __shared__ float qs[NHS];

    float a = 0.f;
    const float* ce = cat_emb + b * NCAT;
    #pragma unroll
    for (int c = part * 16; c < part * 16 + 16; ++c)
        a += ce[c] * Wq[c * NHS + h];
    qpart[part][h] = a;
    __syncthreads();

    if (tid < NHS) {
        float q = 0.f;
        #pragma unroll
        for (int p = 0; p < 8; ++p) q += qpart[p][tid];
        qs[tid] = q * 0.125f;  // fold 1/sqrt(64)
    }
    __syncthreads();

    const float4* wk4 = reinterpret_cast<const float4*>(Wk + tid * NHS);
    const float4* q4  = reinterpret_cast<const float4*>(qs);
    float acc = 0.f;
    #pragma unroll
    for (int i = 0; i < 16; ++i) {
        const float4 w = wk4[i];
        const float4 qq = q4[i];
        acc += w.x * qq.x + w.y * qq.y + w.z * qq.z + w.w * qq.w;
    }
    g_qk[b * NNE + tid] = acc;
}

// ============================================================
// Fused kernel v4: 16-row chunks, smem-staged, ONE barrier.
// grid: (NCHF, NB), 256 threads (8 warps), 32 KB smem.
// Phase 1: warp-per-row loads -> smem + scores -> sscore.
// All warps redundantly compute softmax weights in registers (shfl).
// Phase 2: thread-per-column weighted sum from smem; weights via shfl.
// ============================================================
__global__ void kFuse4(const float* __restrict__ x) {
    const int b = blockIdx.y;
    const int ch = blockIdx.x;
    const int tid = threadIdx.x;
    const int warp = tid >> 5, lane = tid & 31;

    __shared__ float sx[CHR * NNE];   // 32 KB
    __shared__ float sscore[CHR];

    const float4* qkp = reinterpret_cast<const float4*>(g_qk + b * NNE);
    float4 qv[4];
    #pragma unroll
    for (int i = 0; i < 4; ++i) qv[i] = qkp[lane + 32 * i];

    const float4* xbase = reinterpret_cast<const float4*>(
        x + ((size_t)b * NT + (size_t)ch * CHR) * NNE);
    float4* sx4 = reinterpret_cast<float4*>(sx);

    // ---- phase 1: 2 rows per warp ----
    #pragma unroll
    for (int j = 0; j < 2; ++j) {
        const int t = warp + 8 * j;
        const float4* xr = xbase + (size_t)t * (NNE / 4);
        float4 xv[4];
        #pragma unroll
        for (int i = 0; i < 4; ++i) xv[i] = xr[lane + 32 * i];

        float d = 0.f;
        #pragma unroll
        for (int i = 0; i < 4; ++i)
            d += xv[i].x * qv[i].x + xv[i].y * qv[i].y +
                 xv[i].z * qv[i].z + xv[i].w * qv[i].w;

        #pragma unroll
        for (int i = 0; i < 4; ++i)
            sx4[t * (NNE / 4) + lane + 32 * i] = xv[i];

        #pragma unroll
        for (int o = 16; o > 0; o >>= 1)
            d += __shfl_xor_sync(0xffffffffu, d, o);
        if (lane == 0) sscore[t] = d;
    }
    __syncthreads();

    // ---- softmax weights, redundantly in every warp ----
    // lane L holds score of row t = L & 15 (duplicated across halves).
    const float s = sscore[lane & 15];
    float m = s;
    #pragma unroll
    for (int o = 8; o > 0; o >>= 1)   // reduce within 16-group
        m = fmaxf(m, __shfl_xor_sync(0xffffffffu, m, o));
    const float e = __expf(s - m);
    float S = e;
    #pragma unroll
    for (int o = 8; o > 0; o >>= 1)
        S += __shfl_xor_sync(0xffffffffu, S, o);
    if (tid == 0) {
        g_pm[b * NCHF + ch] = m;
        g_ps[b * NCHF + ch] = S;
    }

    // ---- phase 2: thread-per-column weighted sum; weights via shfl ----
    float a0 = 0.f, a1 = 0.f;
    #pragma unroll
    for (int t = 0; t < CHR; ++t) {
        const float wt = __shfl_sync(0xffffffffu, e, t);
        a0 = fmaf(wt, sx[t * NNE + tid],       a0);
        a1 = fmaf(wt, sx[t * NNE + tid + 256], a1);
    }
    float* p = g_pacc + (size_t)(b * NCHF + ch) * NNE;
    p[tid]       = a0;
    p[tid + 256] = a1;
}

// ============================================================
// Kernel E: combine 256 partials (8-way float4) -> xa; xa@Wv; @Wp; LayerNorm
// grid: NB, 1024 threads
// ============================================================
__global__ void kE(const float* __restrict__ Wv,
                   const float* __restrict__ Wp,
                   const float* __restrict__ gamma,
                   const float* __restrict__ beta) {
    const int b = blockIdx.x;
    const int tid = threadIdx.x;
    const int warp = tid >> 5, lane = tid & 31;

    __shared__ float spm[NCHF], sps[NCHF], sf[NCHF];
    __shared__ float4 xpart[8][NNE / 4];   // 16 KB
    __shared__ float xa[NNE];
    __shared__ float wpart[16][NHS];
    __shared__ float outh[NHS];
    __shared__ float red[32];
    __shared__ float bcast;

    if (tid < NCHF) {
        spm[tid] = g_pm[b * NCHF + tid];
        sps[tid] = g_ps[b * NCHF + tid];
    }
    __syncthreads();

    float mb = -INFINITY;
    #pragma unroll 8
    for (int c = 0; c < NCHF; ++c) mb = fmaxf(mb, spm[c]);

    if (tid < NCHF) sf[tid] = __expf(spm[tid] - mb);
    __syncthreads();

    float Sb = 0.f;
    #pragma unroll 8
    for (int c = 0; c < NCHF; ++c) Sb += sps[c] * sf[c];

    // 8-way split of the 256-chunk reduction, float4 columns
    {
        const int col4 = tid & 127;       // float4 column group
        const int part = tid >> 7;        // 8 parts x 32 chunks
        const float4* pp = reinterpret_cast<const float4*>(
            g_pacc + (size_t)(b * NCHF + part * 32) * NNE);
        const float* f = sf + part * 32;
        float4 a = make_float4(0.f, 0.f, 0.f, 0.f);
        #pragma unroll 8
        for (int c = 0; c < 32; ++c) {
            const float4 v = pp[(size_t)c * 128 + col4];
            const float fc = f[c];
            a.x = fmaf(v.x, fc, a.x);
            a.y = fmaf(v.y, fc, a.y);
            a.z = fmaf(v.z, fc, a.z);
            a.w = fmaf(v.w, fc, a.w);
        }
        xpart[part][col4] = a;
    }
    __syncthreads();
    if (tid < 128) {
        float4 a = xpart[0][tid];
        #pragma unroll
        for (int p = 1; p < 8; ++p) {
            const float4 v = xpart[p][tid];
            a.x += v.x; a.y += v.y; a.z += v.z; a.w += v.w;
        }
        const float inv = 1.f / Sb;
        reinterpret_cast<float4*>(xa)[tid] =
            make_float4(a.x * inv, a.y * inv, a.z * inv, a.w * inv);
    }
    __syncthreads();

    // Wv GEMM: out[h] = sum_n xa[n]*Wv[n,h]; 16-way n-split
    {
        const int h = tid & 63;
        const int part = tid >> 6;  // 16 parts x 32 n
        float po = 0.f;
        #pragma unroll
        for (int n = part * 32; n < part * 32 + 32; ++n)
            po = fmaf(xa[n], Wv[n * NHS + h], po);
        wpart[part][h] = po;
    }
    __syncthreads();
    if (tid < NHS) {
        float o = 0.f;
        #pragma unroll
        for (int p = 0; p < 16; ++p) o += wpart[p][tid];
        outh[tid] = o;
    }
    __syncthreads();

    float y = 0.f;
    if (tid < NNE) {
        #pragma unroll
        for (int h2 = 0; h2 < NHS; ++h2)
            y = fmaf(outh[h2], Wp[h2 * NNE + tid], y);
    }

    // LayerNorm over 512 y-values (threads >= 512 contribute 0)
    float s = (tid < NNE) ? y : 0.f;
    #pragma unroll
    for (int o = 16; o > 0; o >>= 1)
        s += __shfl_xor_sync(0xffffffffu, s, o);
    if (lane == 0) red[warp] = s;
    __syncthreads();
    if (tid < 32) {
        float ss2 = red[tid];
        #pragma unroll
        for (int o = 16; o > 0; o >>= 1)
            ss2 += __shfl_xor_sync(0xffffffffu, ss2, o);
        if (tid == 0) bcast = ss2;
    }
    __syncthreads();
    const float mu = bcast * (1.f / NNE);
    __syncthreads();

    const float d = (tid < NNE) ? (y - mu) : 0.f;
    float vs = d * d;
    #pragma unroll
    for (int o = 16; o > 0; o >>= 1)
        vs += __shfl_xor_sync(0xffffffffu, vs, o);
    if (lane == 0) red[warp] = vs;
    __syncthreads();
    if (tid < 32) {
        float ss2 = red[tid];
        #pragma unroll
        for (int o = 16; o > 0; o >>= 1)
            ss2 += __shfl_xor_sync(0xffffffffu, ss2, o);
        if (tid == 0) bcast = ss2;
    }
    __syncthreads();
    const float var = bcast * (1.f / NNE);
    const float rstd = rsqrtf(var + 1e-5f);

    if (tid < NNE)
        g_y[b * NNE + tid] = d * rstd * gamma[tid] + beta[tid];
}

// ============================================================
// Kernel F: broadcast g_y[b,:] to out[b, t, :]; streaming float4 stores
// ============================================================
#define ROWS_F 64
__global__ void kF(float* __restrict__ out) {
    const int b = blockIdx.y;
    const int tid = threadIdx.x;          // 256
    const int col = tid & 127;
    const int half = tid >> 7;

    const float4 val = reinterpret_cast<const float4*>(g_y + b * NNE)[col];

    const int t0 = blockIdx.x * ROWS_F;
    float4* o = reinterpret_cast<float4*>(out + ((size_t)b * NT + t0) * NNE);
    #pragma unroll 8
    for (int r = 0; r < ROWS_F / 2; ++r)
        __stcs(&o[(size_t)(r * 2 + half) * (NNE / 4) + col], val);
}

// ============================================================
extern "C" void kernel_launch(void* const* d_in, const int* in_sizes, int n_in,
                              void* d_out, int out_size) {
    const float* x       = (const float*)d_in[0];
    const float* cat_emb = (const float*)d_in[1];
    const float* Wq      = (const float*)d_in[2];
    const float* Wk      = (const float*)d_in[3];
    const float* Wv      = (const float*)d_in[4];
    const float* Wp      = (const float*)d_in[5];
    const float* gamma   = (const float*)d_in[6];
    const float* beta    = (const float*)d_in[7];
    float* out = (float*)d_out;

    kA<<<NB, 512>>>(cat_emb, Wq, Wk);
    kFuse4<<<dim3(NCHF, NB), 256>>>(x);
    kE<<<NB, 1024>>>(Wv, Wp, gamma, beta);
    kF<<<dim3(NT / ROWS_F, NB), 256>>>(out);
}

// round 8
// speedup vs baseline: 1.5474x; 1.0912x over previous
#include <cuda_runtime.h>
#include <math.h>
#include <stdint.h>

#define NB   32      // batch
#define NT   4096    // sequence
#define NCAT 128
#define NNE  512
#define NHS  64

#define CHR  16              // rows per block in fused kernel
#define NCHF (NT / CHR)      // 256 chunks per batch
#define CHUNK_BYTES (CHR * NNE * 4)  // 32768

// ---- scratch (device globals; no allocations allowed) ----
__device__ float g_qk[NB * NNE];                   // scale * Wk @ (cat_emb @ Wq)
__device__ float g_pm[NB * NCHF];                  // per-chunk local max
__device__ float g_ps[NB * NCHF];                  // per-chunk exp-sum
__device__ float g_pacc[(size_t)NB * NCHF * NNE];  // per-chunk weighted sums
__device__ float g_y[NB * NNE];                    // final per-batch row

// ============================================================
// Kernel A: q = cat_emb@Wq ; qk[n] = 0.125 * Wk[n,:]·q
// ============================================================
__global__ void kA(const float* __restrict__ cat_emb,
                   const float* __restrict__ Wq,
                   const float* __restrict__ Wk) {
    const int b = blockIdx.x;
    const int tid = threadIdx.x;
    const int h = tid & 63;
    const int part = tid >> 6;  // 8 parts x 16 c each

    __shared__ float qpart[8][NHS];
    __shared__ float qs[NHS];

    float a = 0.f;
    const float* ce = cat_emb + b * NCAT;
    #pragma unroll
    for (int c = part * 16; c < part * 16 + 16; ++c)
        a += ce[c] * Wq[c * NHS + h];
    qpart[part][h] = a;
    __syncthreads();

    if (tid < NHS) {
        float q = 0.f;
        #pragma unroll
        for (int p = 0; p < 8; ++p) q += qpart[p][tid];
        qs[tid] = q * 0.125f;
    }
    __syncthreads();

    const float4* wk4 = reinterpret_cast<const float4*>(Wk + tid * NHS);
    const float4* q4  = reinterpret_cast<const float4*>(qs);
    float acc = 0.f;
    #pragma unroll
    for (int i = 0; i < 16; ++i) {
        const float4 w = wk4[i];
        const float4 qq = q4[i];
        acc += w.x * qq.x + w.y * qq.y + w.z * qq.z + w.w * qq.w;
    }
    g_qk[b * NNE + tid] = acc;
}

// ============================================================
// Fused kernel v5b: TMA bulk-copy staging (async DRAM->smem), one pass.
// grid: (NCHF, NB), 256 threads (8 warps), 32 KB smem tile.
// Proper mbarrier init protocol: init -> fence -> __syncthreads -> issue.
// ============================================================
__global__ void kFuse5(const float* __restrict__ x) {
    const int b = blockIdx.y;
    const int ch = blockIdx.x;
    const int tid = threadIdx.x;
    const int warp = tid >> 5, lane = tid & 31;

    __shared__ __align__(128) float sx[CHR * NNE];   // 32 KB
    __shared__ float sscore[CHR];
    __shared__ __align__(8) unsigned long long mbar;

    const uint32_t sx_a = (uint32_t)__cvta_generic_to_shared(sx);
    const uint32_t mb_a = (uint32_t)__cvta_generic_to_shared(&mbar);

    if (tid == 0) {
        asm volatile("mbarrier.init.shared.b64 [%0], 1;" :: "r"(mb_a) : "memory");
        asm volatile("fence.proxy.async.shared::cta;" ::: "memory");
    }
    __syncthreads();   // all threads see initialized mbarrier before waiting

    if (tid == 0) {
        asm volatile("mbarrier.arrive.expect_tx.shared.b64 _, [%0], %1;"
                     :: "r"(mb_a), "r"((uint32_t)CHUNK_BYTES) : "memory");
        const float* src = x + ((size_t)b * NT + (size_t)ch * CHR) * NNE;
        asm volatile(
            "cp.async.bulk.shared::cluster.global.mbarrier::complete_tx::bytes "
            "[%0], [%1], %2, [%3];"
            :: "r"(sx_a), "l"(src), "r"((uint32_t)CHUNK_BYTES), "r"(mb_a)
            : "memory");
    }

    // qk into registers while the bulk copy is in flight
    const float4* qkp = reinterpret_cast<const float4*>(g_qk + b * NNE);
    float4 qv[4];
    #pragma unroll
    for (int i = 0; i < 4; ++i) qv[i] = qkp[lane + 32 * i];

    // wait for the bulk copy (phase 0, acquire ordering for smem reads)
    {
        uint32_t done;
        asm volatile(
            "{\n\t.reg .pred p;\n\t"
            "mbarrier.try_wait.parity.acquire.cta.shared::cta.b64 p, [%1], 0;\n\t"
            "selp.b32 %0, 1, 0, p;\n\t}"
            : "=r"(done) : "r"(mb_a) : "memory");
        while (!done) {
            asm volatile(
                "{\n\t.reg .pred p;\n\t"
                "mbarrier.try_wait.parity.acquire.cta.shared::cta.b64 p, [%1], 0, 0x989680;\n\t"
                "selp.b32 %0, 1, 0, p;\n\t}"
                : "=r"(done) : "r"(mb_a) : "memory");
        }
    }

    const float4* sx4c = reinterpret_cast<const float4*>(sx);

    // ---- scores: 2 rows per warp, from smem ----
    #pragma unroll
    for (int j = 0; j < 2; ++j) {
        const int t = warp + 8 * j;
        float d = 0.f;
        #pragma unroll
        for (int i = 0; i < 4; ++i) {
            const float4 xv = sx4c[t * (NNE / 4) + lane + 32 * i];
            d += xv.x * qv[i].x + xv.y * qv[i].y +
                 xv.z * qv[i].z + xv.w * qv[i].w;
        }
        #pragma unroll
        for (int o = 16; o > 0; o >>= 1)
            d += __shfl_xor_sync(0xffffffffu, d, o);
        if (lane == 0) sscore[t] = d;
    }
    __syncthreads();

    // ---- softmax weights, redundantly in every warp ----
    const float s = sscore[lane & 15];
    float m = s;
    #pragma unroll
    for (int o = 8; o > 0; o >>= 1)
        m = fmaxf(m, __shfl_xor_sync(0xffffffffu, m, o));
    const float e = __expf(s - m);
    float S = e;
    #pragma unroll
    for (int o = 8; o > 0; o >>= 1)
        S += __shfl_xor_sync(0xffffffffu, S, o);
    if (tid == 0) {
        g_pm[b * NCHF + ch] = m;
        g_ps[b * NCHF + ch] = S;
    }

    // ---- phase 2: thread-per-column weighted sum; weights via shfl ----
    float a0 = 0.f, a1 = 0.f;
    #pragma unroll
    for (int t = 0; t < CHR; ++t) {
        const float wt = __shfl_sync(0xffffffffu, e, t);
        a0 = fmaf(wt, sx[t * NNE + tid],       a0);
        a1 = fmaf(wt, sx[t * NNE + tid + 256], a1);
    }
    float* p = g_pacc + (size_t)(b * NCHF + ch) * NNE;
    p[tid]       = a0;
    p[tid + 256] = a1;
}

// ============================================================
// Kernel E: combine 256 partials (8-way float4) -> xa; xa@Wv; @Wp; LayerNorm
// grid: NB, 1024 threads
// ============================================================
__global__ void kE(const float* __restrict__ Wv,
                   const float* __restrict__ Wp,
                   const float* __restrict__ gamma,
                   const float* __restrict__ beta) {
    const int b = blockIdx.x;
    const int tid = threadIdx.x;
    const int warp = tid >> 5, lane = tid & 31;

    __shared__ float spm[NCHF], sps[NCHF], sf[NCHF];
    __shared__ float4 xpart[8][NNE / 4];
    __shared__ float xa[NNE];
    __shared__ float wpart[16][NHS];
    __shared__ float outh[NHS];
    __shared__ float red[32];
    __shared__ float bcast;

    if (tid < NCHF) {
        spm[tid] = g_pm[b * NCHF + tid];
        sps[tid] = g_ps[b * NCHF + tid];
    }
    __syncthreads();

    float mb = -INFINITY;
    #pragma unroll 8
    for (int c = 0; c < NCHF; ++c) mb = fmaxf(mb, spm[c]);

    if (tid < NCHF) sf[tid] = __expf(spm[tid] - mb);
    __syncthreads();

    float Sb = 0.f;
    #pragma unroll 8
    for (int c = 0; c < NCHF; ++c) Sb += sps[c] * sf[c];

    {
        const int col4 = tid & 127;
        const int part = tid >> 7;
        const float4* pp = reinterpret_cast<const float4*>(
            g_pacc + (size_t)(b * NCHF + part * 32) * NNE);
        const float* f = sf + part * 32;
        float4 a = make_float4(0.f, 0.f, 0.f, 0.f);
        #pragma unroll 8
        for (int c = 0; c < 32; ++c) {
            const float4 v = pp[(size_t)c * 128 + col4];
            const float fc = f[c];
            a.x = fmaf(v.x, fc, a.x);
            a.y = fmaf(v.y, fc, a.y);
            a.z = fmaf(v.z, fc, a.z);
            a.w = fmaf(v.w, fc, a.w);
        }
        xpart[part][col4] = a;
    }
    __syncthreads();
    if (tid < 128) {
        float4 a = xpart[0][tid];
        #pragma unroll
        for (int p = 1; p < 8; ++p) {
            const float4 v = xpart[p][tid];
            a.x += v.x; a.y += v.y; a.z += v.z; a.w += v.w;
        }
        const float inv = 1.f / Sb;
        reinterpret_cast<float4*>(xa)[tid] =
            make_float4(a.x * inv, a.y * inv, a.z * inv, a.w * inv);
    }
    __syncthreads();

    {
        const int h = tid & 63;
        const int part = tid >> 6;
        float po = 0.f;
        #pragma unroll
        for (int n = part * 32; n < part * 32 + 32; ++n)
            po = fmaf(xa[n], Wv[n * NHS + h], po);
        wpart[part][h] = po;
    }
    __syncthreads();
    if (tid < NHS) {
        float o = 0.f;
        #pragma unroll
        for (int p = 0; p < 16; ++p) o += wpart[p][tid];
        outh[tid] = o;
    }
    __syncthreads();

    float y = 0.f;
    if (tid < NNE) {
        #pragma unroll
        for (int h2 = 0; h2 < NHS; ++h2)
            y = fmaf(outh[h2], Wp[h2 * NNE + tid], y);
    }

    float s = (tid < NNE) ? y : 0.f;
    #pragma unroll
    for (int o = 16; o > 0; o >>= 1)
        s += __shfl_xor_sync(0xffffffffu, s, o);
    if (lane == 0) red[warp] = s;
    __syncthreads();
    if (tid < 32) {
        float ss2 = red[tid];
        #pragma unroll
        for (int o = 16; o > 0; o >>= 1)
            ss2 += __shfl_xor_sync(0xffffffffu, ss2, o);
        if (tid == 0) bcast = ss2;
    }
    __syncthreads();
    const float mu = bcast * (1.f / NNE);
    __syncthreads();

    const float d = (tid < NNE) ? (y - mu) : 0.f;
    float vs = d * d;
    #pragma unroll
    for (int o = 16; o > 0; o >>= 1)
        vs += __shfl_xor_sync(0xffffffffu, vs, o);
    if (lane == 0) red[warp] = vs;
    __syncthreads();
    if (tid < 32) {
        float ss2 = red[tid];
        #pragma unroll
        for (int o = 16; o > 0; o >>= 1)
            ss2 += __shfl_xor_sync(0xffffffffu, ss2, o);
        if (tid == 0) bcast = ss2;
    }
    __syncthreads();
    const float var = bcast * (1.f / NNE);
    const float rstd = rsqrtf(var + 1e-5f);

    if (tid < NNE)
        g_y[b * NNE + tid] = d * rstd * gamma[tid] + beta[tid];
}

// ============================================================
// Kernel F: broadcast g_y[b,:] to out[b, t, :]; streaming float4 stores
// ============================================================
#define ROWS_F 64
__global__ void kF(float* __restrict__ out) {
    const int b = blockIdx.y;
    const int tid = threadIdx.x;          // 256
    const int col = tid & 127;
    const int half = tid >> 7;

    const float4 val = reinterpret_cast<const float4*>(g_y + b * NNE)[col];

    const int t0 = blockIdx.x * ROWS_F;
    float4* o = reinterpret_cast<float4*>(out + ((size_t)b * NT + t0) * NNE);
    #pragma unroll 8
    for (int r = 0; r < ROWS_F / 2; ++r)
        __stcs(&o[(size_t)(r * 2 + half) * (NNE / 4) + col], val);
}

// ============================================================
extern "C" void kernel_launch(void* const* d_in, const int* in_sizes, int n_in,
                              void* d_out, int out_size) {
    const float* x       = (const float*)d_in[0];
    const float* cat_emb = (const float*)d_in[1];
    const float* Wq      = (const float*)d_in[2];
    const float* Wk      = (const float*)d_in[3];
    const float* Wv      = (const float*)d_in[4];
    const float* Wp      = (const float*)d_in[5];
    const float* gamma   = (const float*)d_in[6];
    const float* beta    = (const float*)d_in[7];
    float* out = (float*)d_out;

    kA<<<NB, 512>>>(cat_emb, Wq, Wk);
    kFuse5<<<dim3(NCHF, NB), 256>>>(x);
    kE<<<NB, 1024>>>(Wv, Wp, gamma, beta);
    kF<<<dim3(NT / ROWS_F, NB), 256>>>(out);
}